// round 8
// baseline (speedup 1.0000x reference)
#include <cuda_runtime.h>
#include <cuda_bf16.h>
#include <cstdint>

// Shapes (fixed by the problem)
#define BB 8
#define SS 256
#define HH 512
#define GG 8
#define LL 16
#define HD 64
#define LHD (LL*HD)   // 1024

// Scratch (device globals — no allocation allowed)
__device__ float d_Q[BB*SS*HH];
__device__ float d_K[BB*SS*HH];
__device__ float d_V[BB*SS*LHD];
__device__ float d_G[BB*GG*SS*SS];
__device__ float d_A[BB*LL*SS*SS];
__device__ float d_O[BB*SS*LHD];

__device__ __forceinline__ unsigned f2tf32(float x) {
    unsigned r;
    asm("cvt.rna.tf32.f32 %0, %1;" : "=r"(r) : "f"(x));
    return r;
}

__device__ __forceinline__ void mma_tf32(float* c, const unsigned* a, const unsigned* b) {
    asm volatile(
        "mma.sync.aligned.m16n8k8.row.col.f32.tf32.tf32.f32 "
        "{%0,%1,%2,%3}, {%4,%5,%6,%7}, {%8,%9}, {%0,%1,%2,%3};"
        : "+f"(c[0]), "+f"(c[1]), "+f"(c[2]), "+f"(c[3])
        : "r"(a[0]), "r"(a[1]), "r"(a[2]), "r"(a[3]), "r"(b[0]), "r"(b[1]));
}

__device__ __forceinline__ void cp16(unsigned dst, const void* src) {
    asm volatile("cp.async.ca.shared.global [%0], [%1], 16;" :: "r"(dst), "l"(src));
}
__device__ __forceinline__ void cp_commit() {
    asm volatile("cp.async.commit_group;");
}
template <int N>
__device__ __forceinline__ void cp_wait() {
    asm volatile("cp.async.wait_group %0;" :: "n"(N));
}

// ---------------------------------------------------------------------------
// TF32 GEMM with cp.async 3-stage pipeline. C[M,N] = A[M,K] @ B[K,N] (+bias)
// Block tile 128x64, K-tile 16, 256 threads (8 warps: 4x2 of 32x32 warp tiles).
// MODE 0: plain. MODE 1: av-batched (z->(b,l)). MODE 2: dual-output (Q|K).
// ---------------------------------------------------------------------------
template <int MODE>
__global__ void __launch_bounds__(256)
gemm_tf32_kernel(const float* __restrict__ A, int lda,
                 const float* __restrict__ B, int ldb,
                 const float* __restrict__ bias,
                 float* __restrict__ C, int ldc,
                 int K,
                 const float* __restrict__ B2,
                 float* __restrict__ C2) {
    int col0 = blockIdx.x * 64;
    if (MODE == 1) {
        const int z = blockIdx.z;
        const int b = z >> 4, l = z & 15;
        A += (size_t)z * SS * SS;
        const size_t off = (size_t)b * SS * LHD + (size_t)l * HD;
        B += off; C += off;
    }
    if (MODE == 2) {
        if (col0 >= HH) { B = B2; C = C2; col0 -= HH; }
    }
    const int row0 = blockIdx.y * 128;

    __shared__ float As[3][128][20];   // [m][k]
    __shared__ float Bs[3][16][72];    // [k][n]

    const int tid = threadIdx.x;
    const int warp = tid >> 5, lane = tid & 31;
    const int gid = lane >> 2, tig = lane & 3;
    const int wm = warp & 3, wn = warp >> 2;

    float c[2][4][4] = {};

    const int a_r = tid >> 2;
    const int a_c4 = (tid & 3) * 4;
    const int b_k = tid >> 4;
    const int b_n4 = (tid & 15) * 4;

    const float* Ag0 = A + (size_t)(row0 + a_r) * lda + a_c4;
    const float* Ag1 = A + (size_t)(row0 + a_r + 64) * lda + a_c4;
    const float* Bg  = B + (size_t)b_k * ldb + col0 + b_n4;

    unsigned dA0[3], dA1[3], dB[3];
    #pragma unroll
    for (int s = 0; s < 3; s++) {
        dA0[s] = (unsigned)__cvta_generic_to_shared(&As[s][a_r][a_c4]);
        dA1[s] = (unsigned)__cvta_generic_to_shared(&As[s][a_r + 64][a_c4]);
        dB[s]  = (unsigned)__cvta_generic_to_shared(&Bs[s][b_k][b_n4]);
    }

    const int KT = K / 16;
    #pragma unroll
    for (int pf = 0; pf < 2; pf++) {
        cp16(dA0[pf], Ag0 + pf * 16);
        cp16(dA1[pf], Ag1 + pf * 16);
        cp16(dB[pf],  Bg + (size_t)(pf * 16) * ldb);
        cp_commit();
    }

    for (int kt = 0; kt < KT; kt++) {
        cp_wait<1>();
        __syncthreads();
        const int st = kt % 3;
        #pragma unroll
        for (int ks = 0; ks < 16; ks += 8) {
            unsigned af[2][4], bf[4][2];
            #pragma unroll
            for (int mt = 0; mt < 2; mt++) {
                const int mb = wm * 32 + mt * 16 + gid;
                af[mt][0] = f2tf32(As[st][mb][ks + tig]);
                af[mt][1] = f2tf32(As[st][mb + 8][ks + tig]);
                af[mt][2] = f2tf32(As[st][mb][ks + tig + 4]);
                af[mt][3] = f2tf32(As[st][mb + 8][ks + tig + 4]);
            }
            #pragma unroll
            for (int nt = 0; nt < 4; nt++) {
                const int nb = wn * 32 + nt * 8 + gid;
                bf[nt][0] = f2tf32(Bs[st][ks + tig][nb]);
                bf[nt][1] = f2tf32(Bs[st][ks + tig + 4][nb]);
            }
            #pragma unroll
            for (int mt = 0; mt < 2; mt++)
                #pragma unroll
                for (int nt = 0; nt < 4; nt++)
                    mma_tf32(c[mt][nt], af[mt], bf[nt]);
        }
        const int ktn = kt + 2;
        if (ktn < KT) {
            const int sn = ktn % 3;
            cp16(dA0[sn], Ag0 + ktn * 16);
            cp16(dA1[sn], Ag1 + ktn * 16);
            cp16(dB[sn],  Bg + (size_t)(ktn * 16) * ldb);
        }
        cp_commit();
    }

    #pragma unroll
    for (int mt = 0; mt < 2; mt++) {
        #pragma unroll
        for (int nt = 0; nt < 4; nt++) {
            const int r = row0 + wm * 32 + mt * 16 + gid;
            const int cc = col0 + wn * 32 + nt * 8 + 2 * tig;
            float b0 = 0.f, b1 = 0.f;
            if (MODE == 0 && bias) { b0 = bias[cc]; b1 = bias[cc + 1]; }
            C[(size_t)r * ldc + cc]           = c[mt][nt][0] + b0;
            C[(size_t)r * ldc + cc + 1]       = c[mt][nt][1] + b1;
            C[(size_t)(r + 8) * ldc + cc]     = c[mt][nt][2] + b0;
            C[(size_t)(r + 8) * ldc + cc + 1] = c[mt][nt][3] + b1;
        }
    }
}

// ---------------------------------------------------------------------------
// Scores (TF32 MMA + cp.async): G = scale*Q·K^T + sp + ed, per (b,g).
// ---------------------------------------------------------------------------
__global__ void __launch_bounds__(256)
scores_tf32_kernel(const float* __restrict__ sp, const float* __restrict__ ed) {
    const int z = blockIdx.z;
    const int b = z >> 3, g = z & 7;
    const int row0 = blockIdx.y * 128;   // s
    const int col0 = blockIdx.x * 64;    // t

    __shared__ float As[3][128][20];     // Q [s][d]
    __shared__ float Bs[3][64][20];      // K [t][d]

    const int tid = threadIdx.x;
    const int warp = tid >> 5, lane = tid & 31;
    const int gid = lane >> 2, tig = lane & 3;
    const int wm = warp & 3, wn = warp >> 2;

    float c[2][4][4] = {};

    const int a_r = tid >> 2;
    const int a_c4 = (tid & 3) * 4;
    const int bn = tid >> 2;
    const int bk4 = (tid & 3) * 4;

    const float* Qb = d_Q + ((size_t)(b * SS)) * HH + g * 64;
    const float* Kb = d_K + ((size_t)(b * SS)) * HH + g * 64;
    const float* Ag0 = Qb + (size_t)(row0 + a_r) * HH + a_c4;
    const float* Ag1 = Qb + (size_t)(row0 + a_r + 64) * HH + a_c4;
    const float* Bg  = Kb + (size_t)(col0 + bn) * HH + bk4;

    unsigned dA0[3], dA1[3], dB[3];
    #pragma unroll
    for (int s = 0; s < 3; s++) {
        dA0[s] = (unsigned)__cvta_generic_to_shared(&As[s][a_r][a_c4]);
        dA1[s] = (unsigned)__cvta_generic_to_shared(&As[s][a_r + 64][a_c4]);
        dB[s]  = (unsigned)__cvta_generic_to_shared(&Bs[s][bn][bk4]);
    }

    #pragma unroll
    for (int pf = 0; pf < 2; pf++) {
        cp16(dA0[pf], Ag0 + pf * 16);
        cp16(dA1[pf], Ag1 + pf * 16);
        cp16(dB[pf],  Bg + pf * 16);
        cp_commit();
    }

    #pragma unroll
    for (int kt = 0; kt < 4; kt++) {
        cp_wait<1>();
        __syncthreads();
        const int st = kt % 3;
        #pragma unroll
        for (int ks = 0; ks < 16; ks += 8) {
            unsigned af[2][4], bf[4][2];
            #pragma unroll
            for (int mt = 0; mt < 2; mt++) {
                const int mb = wm * 32 + mt * 16 + gid;
                af[mt][0] = f2tf32(As[st][mb][ks + tig]);
                af[mt][1] = f2tf32(As[st][mb + 8][ks + tig]);
                af[mt][2] = f2tf32(As[st][mb][ks + tig + 4]);
                af[mt][3] = f2tf32(As[st][mb + 8][ks + tig + 4]);
            }
            #pragma unroll
            for (int nt = 0; nt < 4; nt++) {
                const int nb = wn * 32 + nt * 8 + gid;
                bf[nt][0] = f2tf32(Bs[st][nb][ks + tig]);
                bf[nt][1] = f2tf32(Bs[st][nb][ks + tig + 4]);
            }
            #pragma unroll
            for (int mt = 0; mt < 2; mt++)
                #pragma unroll
                for (int nt = 0; nt < 4; nt++)
                    mma_tf32(c[mt][nt], af[mt], bf[nt]);
        }
        const int ktn = kt + 2;
        if (ktn < 4) {
            const int sn = ktn % 3;
            cp16(dA0[sn], Ag0 + ktn * 16);
            cp16(dA1[sn], Ag1 + ktn * 16);
            cp16(dB[sn],  Bg + ktn * 16);
        }
        cp_commit();
    }

    const float scale = 0.04419417382415922f;  // 512^-0.5
    float* Gb = d_G + ((size_t)z) * SS * SS;
    const float* spb = sp + ((size_t)b) * SS * SS;
    const float* edb = ed + ((size_t)b) * SS * SS;
    #pragma unroll
    for (int mt = 0; mt < 2; mt++) {
        #pragma unroll
        for (int nt = 0; nt < 4; nt++) {
            const int s = row0 + wm * 32 + mt * 16 + gid;
            const int t = col0 + wn * 32 + nt * 8 + 2 * tig;
            size_t i0 = (size_t)s * SS + t;
            size_t i1 = (size_t)(s + 8) * SS + t;
            Gb[i0]     = c[mt][nt][0] * scale + spb[i0] + edb[i0];
            Gb[i0 + 1] = c[mt][nt][1] * scale + spb[i0 + 1] + edb[i0 + 1];
            Gb[i1]     = c[mt][nt][2] * scale + spb[i1] + edb[i1];
            Gb[i1 + 1] = c[mt][nt][3] * scale + spb[i1 + 1] + edb[i1 + 1];
        }
    }
}

// ---------------------------------------------------------------------------
// Fused relu-sum-over-g + diag correction + pad + softmax.
// 512 threads per block, one block per (b,s), warp w = l-head w.
// Diagonal handled by one lane post-hoc (outside the hot loop).
// ---------------------------------------------------------------------------
__global__ void __launch_bounds__(512)
attn_softmax_kernel(const float* __restrict__ p,
                    const float* __restrict__ sigma,
                    const float* __restrict__ eps_diag) {
    const int b = blockIdx.x >> 8;
    const int s = blockIdx.x & 255;
    const int tid = threadIdx.x;
    const int warp = tid >> 5, lane = tid & 31;   // warp == l

    __shared__ float gs[GG][SS];       // 8 KB
    __shared__ float s_p[GG * LL];
    __shared__ float s_sig2[GG];
    __shared__ float s_eps[LL];
    __shared__ int s_nz[GG];

    #pragma unroll
    for (int i = tid; i < GG * SS; i += 512) {
        int g = i >> 8, t = i & 255;
        gs[g][t] = d_G[(((size_t)(b * GG + g)) * SS + s) * SS + t];
    }
    if (tid < GG * LL) s_p[tid] = p[tid];
    if (tid >= 128 && tid < 128 + GG) { float sg = sigma[tid - 128]; s_sig2[tid - 128] = sg * sg; }
    if (tid >= 160 && tid < 160 + LL) s_eps[tid - 160] = eps_diag[(tid - 160) * SS + s];
    __syncthreads();

    // pad check: warps 0..7 scan g = warp
    if (warp < GG) {
        bool nzl = false;
        #pragma unroll
        for (int tt = 0; tt < 8; tt++) nzl |= (gs[warp][lane + tt * 32] != 0.0f);
        unsigned bal = __ballot_sync(0xffffffffu, nzl);
        if (lane == 0) s_nz[warp] = (bal != 0u);
    }
    __syncthreads();
    bool zero_row = false;
    #pragma unroll
    for (int g = 0; g < GG; g++) zero_row |= (s_nz[g] == 0);

    const int l = warp;
    float pl[GG];
    #pragma unroll
    for (int g = 0; g < GG; g++) pl[g] = s_p[g * LL + l];

    // main accumulation, diagonal excluded
    float vals[8];
    #pragma unroll
    for (int tt = 0; tt < 8; tt++) {
        const int t = lane + tt * 32;
        float v = 0.f;
        #pragma unroll
        for (int g = 0; g < GG; g++)
            v += fmaxf(pl[g] * gs[g][t], 0.f);
        vals[tt] = v;
    }
    // the single lane owning t == s redoes its value with the diagonal term
    if (lane == (s & 31)) {
        const float el = s_eps[l];
        float v = 0.f;
        #pragma unroll
        for (int g = 0; g < GG; g++)
            v += fmaxf(pl[g] * (gs[g][s] + s_sig2[g] * el), 0.f);
        vals[s >> 5] = v;
    }

    // warp max
    float m = vals[0];
    #pragma unroll
    for (int tt = 1; tt < 8; tt++) m = fmaxf(m, vals[tt]);
    #pragma unroll
    for (int off = 16; off > 0; off >>= 1) m = fmaxf(m, __shfl_xor_sync(0xffffffffu, m, off));
    // exp in place + warp sum
    float sum = 0.f;
    #pragma unroll
    for (int tt = 0; tt < 8; tt++) { vals[tt] = __expf(vals[tt] - m); sum += vals[tt]; }
    #pragma unroll
    for (int off = 16; off > 0; off >>= 1) sum += __shfl_xor_sync(0xffffffffu, sum, off);
    const float inv = zero_row ? 0.f : (1.0f / sum);

    float* Arow = d_A + (((size_t)(b * LL + l)) * SS + s) * SS;
    #pragma unroll
    for (int tt = 0; tt < 8; tt++) Arow[lane + tt * 32] = vals[tt] * inv;
}

// ---------------------------------------------------------------------------
extern "C" void kernel_launch(void* const* d_in, const int* in_sizes, int n_in,
                              void* d_out, int out_size) {
    (void)in_sizes; (void)n_in; (void)out_size;
    const float* x    = (const float*)d_in[0];
    const float* sp   = (const float*)d_in[1];
    const float* ed   = (const float*)d_in[2];
    const float* Wq   = (const float*)d_in[3];
    const float* Wk   = (const float*)d_in[4];
    const float* Wv   = (const float*)d_in[5];
    const float* bv   = (const float*)d_in[6];
    const float* sig  = (const float*)d_in[7];
    const float* p    = (const float*)d_in[8];
    const float* eps  = (const float*)d_in[9];
    const float* Wout = (const float*)d_in[10];
    const float* bout = (const float*)d_in[11];
    float* out = (float*)d_out;

    float *Qp, *Kp, *Vp, *Ap, *Op;
    cudaGetSymbolAddress((void**)&Qp, d_Q);
    cudaGetSymbolAddress((void**)&Kp, d_K);
    cudaGetSymbolAddress((void**)&Vp, d_V);
    cudaGetSymbolAddress((void**)&Ap, d_A);
    cudaGetSymbolAddress((void**)&Op, d_O);

    dim3 blk(256);
    const int M = BB * SS;  // 2048
    // 1) Q+K fused projection (dual-output), V projection
    gemm_tf32_kernel<2><<<dim3(2 * HH / 64, M / 128), blk>>>(
        x, HH, Wq, HH, nullptr, Qp, HH, HH, Wk, Kp);
    gemm_tf32_kernel<0><<<dim3(LHD / 64, M / 128), blk>>>(
        x, HH, Wv, LHD, bv, Vp, LHD, HH, nullptr, nullptr);
    // 2) scores + bias
    scores_tf32_kernel<<<dim3(SS / 64, SS / 128, BB * GG), blk>>>(sp, ed);
    // 3) relu-sum over g + softmax (warp-per-l, 512 threads)
    attn_softmax_kernel<<<dim3(BB * SS), dim3(512)>>>(p, sig, eps);
    // 4) A @ V (batched over (b,l))
    gemm_tf32_kernel<1><<<dim3(1, SS / 128, BB * LL), blk>>>(
        Ap, SS, Vp, LHD, nullptr, Op, LHD, SS, nullptr, nullptr);
    // 5) output projection
    gemm_tf32_kernel<0><<<dim3(HH / 64, M / 128), blk>>>(
        Op, LHD, Wout, HH, bout, out, HH, LHD, nullptr, nullptr);
}